// round 15
// baseline (speedup 1.0000x reference)
#include <cuda_runtime.h>
#include <cuda_fp16.h>
#include <cstdint>

#define Bv 16
#define Nv 1024
#define Cv 768
#define Hv 12
#define HD 64
#define C3 2304
#define MT (Bv*Nv)   // 16384

// ======================= device scratch =======================
__device__ float g_sig[Bv * C3];
__device__ __half g_xh[(size_t)MT * Cv];
__device__ __half g_w1h[(size_t)C3 * Cv];
__device__ __half g_w2h[(size_t)Cv * Cv];
__device__ __half g_qh[(size_t)MT * Cv];   // (b,h,n,hd) fp16
__device__ __half g_kh[(size_t)MT * Cv];
__device__ __half g_vh[(size_t)MT * Cv];
__device__ __half g_oh[(size_t)MT * Cv];   // (b,n,c) fp16

// ======================= PTX helpers (baseline ISA only) =======================
__device__ __forceinline__ uint32_t smem_u32(const void* p) {
    uint32_t a;
    asm("{ .reg .u64 t; cvta.to.shared.u64 t, %1; cvt.u32.u64 %0, t; }" : "=r"(a) : "l"(p));
    return a;
}
__device__ __forceinline__ void ldm_x4(uint32_t& r0, uint32_t& r1, uint32_t& r2, uint32_t& r3,
                                       uint32_t addr) {
    asm volatile("ldmatrix.sync.aligned.m8n8.x4.shared.b16 {%0,%1,%2,%3}, [%4];"
                 : "=r"(r0), "=r"(r1), "=r"(r2), "=r"(r3) : "r"(addr));
}
__device__ __forceinline__ void ldm_x4_t(uint32_t& r0, uint32_t& r1, uint32_t& r2, uint32_t& r3,
                                         uint32_t addr) {
    asm volatile("ldmatrix.sync.aligned.m8n8.x4.trans.shared.b16 {%0,%1,%2,%3}, [%4];"
                 : "=r"(r0), "=r"(r1), "=r"(r2), "=r"(r3) : "r"(addr));
}
__device__ __forceinline__ void mma_f16(float* d, const uint32_t* a, const uint32_t* b) {
    asm volatile(
        "mma.sync.aligned.m16n8k16.row.col.f32.f16.f16.f32 "
        "{%0,%1,%2,%3}, {%4,%5,%6,%7}, {%8,%9}, {%0,%1,%2,%3};"
        : "+f"(d[0]), "+f"(d[1]), "+f"(d[2]), "+f"(d[3])
        : "r"(a[0]), "r"(a[1]), "r"(a[2]), "r"(a[3]), "r"(b[0]), "r"(b[1]));
}
// fp16-accumulator HMMA (2x rate on some chips — this round's experiment)
__device__ __forceinline__ void mma_f16acc(uint32_t* d, const uint32_t* a, const uint32_t* b) {
    asm volatile(
        "mma.sync.aligned.m16n8k16.row.col.f16.f16.f16.f16 "
        "{%0,%1}, {%2,%3,%4,%5}, {%6,%7}, {%0,%1};"
        : "+r"(d[0]), "+r"(d[1])
        : "r"(a[0]), "r"(a[1]), "r"(a[2]), "r"(a[3]), "r"(b[0]), "r"(b[1]));
}
__device__ __forceinline__ void cp16(uint32_t dst, const void* src) {
    asm volatile("cp.async.cg.shared.global [%0], [%1], 16;" :: "r"(dst), "l"(src));
}
#define CP_COMMIT() asm volatile("cp.async.commit_group;" ::: "memory")
#define CP_WAIT1()  asm volatile("cp.async.wait_group 1;" ::: "memory")

__device__ __forceinline__ uint32_t pack2h(float x, float y) {
    __half2 h = __floats2half2_rn(x, y);
    return *(uint32_t*)&h;
}
__device__ __forceinline__ float fexp2(float x) {
    float r;
    asm("ex2.approx.ftz.f32 %0, %1;" : "=f"(r) : "f"(x));
    return r;
}
#define EXSCALE 0.1803368801f   // 0.125 * log2(e)

// ======================= prep: gate + converts, MLP=4 per thread =======================
#define N8X  (MT * Cv / 8)
#define N8W1 (C3 * Cv / 8)
#define N8W2 (Cv * Cv / 8)
#define N8TOT (N8X + N8W1 + N8W2)
#define GATEN (Bv * C3)

__global__ void prep_kernel(const float* __restrict__ x,
                            const float* __restrict__ w1,
                            const float* __restrict__ w2,
                            const float* __restrict__ alpha,
                            const int* __restrict__ label) {
    const int base = blockIdx.x * 1024 + threadIdx.x;
    #pragma unroll
    for (int it = 0; it < 4; it++) {
        int i = base + it * 256;
        if (i >= N8TOT) break;
        const float* src;
        __half* dst;
        size_t j;
        if (i < N8X)            { src = x;  dst = g_xh;  j = i; }
        else if (i < N8X + N8W1){ src = w1; dst = g_w1h; j = i - N8X; }
        else                    { src = w2; dst = g_w2h; j = i - N8X - N8W1; }
        const float4* s = (const float4*)src + j * 2;
        float4 v0 = s[0], v1 = s[1];
        __half h[8] = {
            __float2half_rn(v0.x), __float2half_rn(v0.y), __float2half_rn(v0.z), __float2half_rn(v0.w),
            __float2half_rn(v1.x), __float2half_rn(v1.y), __float2half_rn(v1.z), __float2half_rn(v1.w)
        };
        *(uint4*)(dst + j * 8) = *(uint4*)h;
    }
    #pragma unroll
    for (int it = 0; it < 4; it++) {
        int i = base + it * 256;
        if (i < GATEN) {
            int b = i / C3;
            int d = i - b * C3;
            float a = alpha[(size_t)label[b] * C3 + d];
            g_sig[i] = 1.0f / (1.0f + __expf(-a));
        }
    }
}

// ======================= qkv GEMM: 128x128 tile, 2-stage (unchanged R14) =======================
#define LDP 40
#define TILEB (128*LDP*2)           // 10240
#define BUFB  (2*TILEB)             // 20480
#define SM_BYTES (2*BUFB)           // 40960

__global__ __launch_bounds__(256, 2)
void qkv_gemm(const float* __restrict__ bias) {
    extern __shared__ __align__(16) char sm[];
    const uint32_t sb = smem_u32(sm);

    const int tid = threadIdx.x;
    const int wid = tid >> 5;
    const int lane = tid & 31;
    const int m0 = blockIdx.y * 128;
    const int n0 = blockIdx.x * 128;
    const int wm = (wid & 1) * 64;
    const int wn = (wid >> 1) * 32;

    const int srow = tid >> 2;
    const int sg = tid & 3;

    const int grp = lane >> 3, lr = lane & 7;
    const int aRow = (grp & 1) * 8 + lr;
    const int aCol = (grp >> 1) * 8;
    const int bRow = (grp >> 1) * 8 + lr;
    const int bCol = (grp & 1) * 8;

    float acc[4][4][4] = {};

    auto issue = [&](int kc, int bsel) {
        const int k0 = kc * 32;
        const __half* s0 = g_xh + (size_t)m0 * Cv + k0;
        const __half* s1 = g_w1h + (size_t)n0 * Cv + k0;
        const uint32_t db = sb + bsel * BUFB;
        #pragma unroll
        for (int j = 0; j < 2; j++) {
            int row = srow + j * 64;
            uint32_t doff = (uint32_t)(row * LDP + sg * 8) * 2;
            size_t goff = (size_t)row * Cv + sg * 8;
            cp16(db + 0 * TILEB + doff, s0 + goff);
            cp16(db + 1 * TILEB + doff, s1 + goff);
        }
    };

    issue(0, 0); CP_COMMIT();
    issue(1, 1); CP_COMMIT();

    for (int kc = 0; kc < 24; kc++) {
        CP_WAIT1();
        __syncthreads();
        const uint32_t db = sb + (kc & 1) * BUFB;

        #pragma unroll
        for (int kk = 0; kk < 2; kk++) {
            uint32_t bh[4][2];
            #pragma unroll
            for (int np = 0; np < 2; np++) {
                uint32_t off = (uint32_t)((wn + np * 16 + bRow) * LDP + kk * 16 + bCol) * 2;
                uint32_t r0, r1, r2, r3;
                ldm_x4(r0, r1, r2, r3, db + TILEB + off);
                bh[np * 2][0] = r0; bh[np * 2][1] = r1;
                bh[np * 2 + 1][0] = r2; bh[np * 2 + 1][1] = r3;
            }
            #pragma unroll
            for (int mi = 0; mi < 4; mi++) {
                uint32_t ah[4];
                uint32_t off = (uint32_t)((wm + mi * 16 + aRow) * LDP + kk * 16 + aCol) * 2;
                ldm_x4(ah[0], ah[1], ah[2], ah[3], db + off);
                #pragma unroll
                for (int nj = 0; nj < 4; nj++)
                    mma_f16(acc[mi][nj], ah, bh[nj]);
            }
        }
        __syncthreads();
        if (kc + 2 < 24) issue(kc + 2, kc & 1);
        CP_COMMIT();
    }

    const int tq = n0 / Cv;
    #pragma unroll
    for (int mi = 0; mi < 4; mi++) {
        #pragma unroll
        for (int nj = 0; nj < 4; nj++) {
            int r = m0 + wm + mi * 16 + (lane >> 2);
            int c = n0 + wn + nj * 8 + 2 * (lane & 3);
            #pragma unroll
            for (int half = 0; half < 2; half++) {
                int rr = r + half * 8;
                float v0 = acc[mi][nj][half * 2 + 0];
                float v1 = acc[mi][nj][half * 2 + 1];
                float2 bi = *(const float2*)(bias + c);
                int b = rr >> 10;
                int n = rr & 1023;
                float2 sg2 = *(const float2*)(g_sig + b * C3 + c);
                float ox = (v0 + bi.x) * sg2.x;
                float oy = (v1 + bi.y) * sg2.y;
                int rem = c - tq * Cv;
                int h = rem >> 6;
                int e = rem & 63;
                size_t idx = ((size_t)(b * Hv + h) * Nv + n) * HD + e;
                __half* dst = (tq == 0) ? g_qh : (tq == 1) ? g_kh : g_vh;
                *(uint32_t*)(dst + idx) = pack2h(ox, oy);
            }
        }
    }
}

// ======================= proj GEMM: 128x128 tile, 2-stage (unchanged R14) =======================
__global__ __launch_bounds__(256, 2)
void proj_gemm(const float* __restrict__ bias, float* __restrict__ out) {
    extern __shared__ __align__(16) char sm[];
    const uint32_t sb = smem_u32(sm);

    const int tid = threadIdx.x;
    const int wid = tid >> 5;
    const int lane = tid & 31;
    const int m0 = blockIdx.y * 128;
    const int n0 = blockIdx.x * 128;
    const int wm = (wid & 1) * 64;
    const int wn = (wid >> 1) * 32;

    const int srow = tid >> 2;
    const int sg = tid & 3;

    const int grp = lane >> 3, lr = lane & 7;
    const int aRow = (grp & 1) * 8 + lr;
    const int aCol = (grp >> 1) * 8;
    const int bRow = (grp >> 1) * 8 + lr;
    const int bCol = (grp & 1) * 8;

    float acc[4][4][4] = {};

    auto issue = [&](int kc, int bsel) {
        const int k0 = kc * 32;
        const __half* s0 = g_oh + (size_t)m0 * Cv + k0;
        const __half* s1 = g_w2h + (size_t)n0 * Cv + k0;
        const uint32_t db = sb + bsel * BUFB;
        #pragma unroll
        for (int j = 0; j < 2; j++) {
            int row = srow + j * 64;
            uint32_t doff = (uint32_t)(row * LDP + sg * 8) * 2;
            size_t goff = (size_t)row * Cv + sg * 8;
            cp16(db + 0 * TILEB + doff, s0 + goff);
            cp16(db + 1 * TILEB + doff, s1 + goff);
        }
    };

    issue(0, 0); CP_COMMIT();
    issue(1, 1); CP_COMMIT();

    for (int kc = 0; kc < 24; kc++) {
        CP_WAIT1();
        __syncthreads();
        const uint32_t db = sb + (kc & 1) * BUFB;

        #pragma unroll
        for (int kk = 0; kk < 2; kk++) {
            uint32_t bh[4][2];
            #pragma unroll
            for (int np = 0; np < 2; np++) {
                uint32_t off = (uint32_t)((wn + np * 16 + bRow) * LDP + kk * 16 + bCol) * 2;
                uint32_t r0, r1, r2, r3;
                ldm_x4(r0, r1, r2, r3, db + TILEB + off);
                bh[np * 2][0] = r0; bh[np * 2][1] = r1;
                bh[np * 2 + 1][0] = r2; bh[np * 2 + 1][1] = r3;
            }
            #pragma unroll
            for (int mi = 0; mi < 4; mi++) {
                uint32_t ah[4];
                uint32_t off = (uint32_t)((wm + mi * 16 + aRow) * LDP + kk * 16 + aCol) * 2;
                ldm_x4(ah[0], ah[1], ah[2], ah[3], db + off);
                #pragma unroll
                for (int nj = 0; nj < 4; nj++)
                    mma_f16(acc[mi][nj], ah, bh[nj]);
            }
        }
        __syncthreads();
        if (kc + 2 < 24) issue(kc + 2, kc & 1);
        CP_COMMIT();
    }

    #pragma unroll
    for (int mi = 0; mi < 4; mi++) {
        #pragma unroll
        for (int nj = 0; nj < 4; nj++) {
            int r = m0 + wm + mi * 16 + (lane >> 2);
            int c = n0 + wn + nj * 8 + 2 * (lane & 3);
            #pragma unroll
            for (int half = 0; half < 2; half++) {
                int rr = r + half * 8;
                float2 bi = *(const float2*)(bias + c);
                float2 o;
                o.x = acc[mi][nj][half * 2 + 0] + bi.x;
                o.y = acc[mi][nj][half * 2 + 1] + bi.y;
                *(float2*)(out + (size_t)rr * Cv + c) = o;
            }
        }
    }
}

// ======================= attention: fp16-acc QK^T (experiment), fp32-acc PV =======================
#define LDV 72
#define VTILEB (64*LDV*2)           // 9216
#define ABUFB (2*VTILEB)            // 18432
#define ASM_BYTES (2*ABUFB)         // 36864

__global__ __launch_bounds__(256, 2) void attn_mma() {
    extern __shared__ __align__(16) char sm[];
    const uint32_t sb = smem_u32(sm);

    const int tid = threadIdx.x;
    const int wid = tid >> 5;
    const int lane = tid & 31;
    const int bh = blockIdx.y;
    const size_t head_base = (size_t)bh * Nv * HD;
    const int q0 = blockIdx.x * 128 + wid * 16;

    const int grp = lane >> 3, lr = lane & 7;
    const int bRow = (grp >> 1) * 8 + lr;
    const int bCol = (grp & 1) * 8;
    const int vRow = lane & 15;
    const int vCol = (lane >> 4) * 8;

    const int srow = tid >> 3;
    const int sg = tid & 7;

    // ---- Q fragments (fp16) direct from gmem ----
    const int qrow0 = q0 + (lane >> 2);
    const int kcol = (lane & 3) * 2;
    uint32_t qh[4][4];
    {
        const size_t base0 = head_base + (size_t)qrow0 * HD;
        const size_t base1 = base0 + 8 * HD;
        #pragma unroll
        for (int s = 0; s < 4; s++) {
            qh[s][0] = *(const uint32_t*)(g_qh + base0 + s * 16 + kcol);
            qh[s][1] = *(const uint32_t*)(g_qh + base1 + s * 16 + kcol);
            qh[s][2] = *(const uint32_t*)(g_qh + base0 + s * 16 + 8 + kcol);
            qh[s][3] = *(const uint32_t*)(g_qh + base1 + s * 16 + 8 + kcol);
        }
    }

    auto issue = [&](int kt, int bsel) {
        const __half* s0 = g_kh + head_base + (size_t)kt * 64 * HD;
        const __half* s1 = g_vh + head_base + (size_t)kt * 64 * HD;
        const uint32_t db = sb + bsel * ABUFB;
        #pragma unroll
        for (int j = 0; j < 2; j++) {
            int row = srow + j * 32;
            uint32_t doff = (uint32_t)(row * LDV + sg * 8) * 2;
            size_t goff = (size_t)row * HD + sg * 8;
            cp16(db + 0 * VTILEB + doff, s0 + goff);
            cp16(db + 1 * VTILEB + doff, s1 + goff);
        }
    };

    float oacc[8][4] = {};
    float l0 = 0.f, l1 = 0.f;

    issue(0, 0); CP_COMMIT();
    issue(1, 1); CP_COMMIT();

    for (int kt = 0; kt < 16; kt++) {
        CP_WAIT1();
        __syncthreads();
        const uint32_t db = sb + (kt & 1) * ABUFB;
        const uint32_t khb = db;
        const uint32_t vhb = db + VTILEB;

        // ---- S = Q.K^T with fp16 accumulator, exp2, pack P ----
        uint32_t pa[4][4];
        #pragma unroll
        for (int np = 0; np < 4; np++) {
            uint32_t sc0[2] = {0u, 0u}, sc1[2] = {0u, 0u};   // half2 accumulators
            #pragma unroll
            for (int s = 0; s < 4; s++) {
                uint32_t off = (uint32_t)((np * 16 + bRow) * LDV + s * 16 + bCol) * 2;
                uint32_t h0, h1, h2, h3;
                ldm_x4(h0, h1, h2, h3, khb + off);
                uint32_t bh0[2] = {h0, h1}, bh1[2] = {h2, h3};
                mma_f16acc(sc0, qh[s], bh0);
                mma_f16acc(sc1, qh[s], bh1);
            }
            // sc0[0] = (row r,  cols c0,c1), sc0[1] = (row r+8, cols c0,c1)
            // sc1[0] = (row r,  cols c8+..), sc1[1] = (row r+8, cols c8+..)
            float2 f00 = __half22float2(*(__half2*)&sc0[0]);
            float2 f01 = __half22float2(*(__half2*)&sc0[1]);
            float2 f10 = __half22float2(*(__half2*)&sc1[0]);
            float2 f11 = __half22float2(*(__half2*)&sc1[1]);
            float p00 = fexp2(f00.x * EXSCALE), p01 = fexp2(f00.y * EXSCALE);
            float p02 = fexp2(f01.x * EXSCALE), p03 = fexp2(f01.y * EXSCALE);
            float p10 = fexp2(f10.x * EXSCALE), p11 = fexp2(f10.y * EXSCALE);
            float p12 = fexp2(f11.x * EXSCALE), p13 = fexp2(f11.y * EXSCALE);
            // l0: row r (p00,p01 cols lo + p10,p11 cols hi); l1: row r+8
            l0 += (p00 + p01) + (p10 + p11);
            l1 += (p02 + p03) + (p12 + p13);
            pa[np][0] = pack2h(p00, p01);   // A-frag a0: (r, k pair)
            pa[np][1] = pack2h(p02, p03);   // a1: (r+8, k pair)
            pa[np][2] = pack2h(p10, p11);   // a2: (r, k+8 pair)
            pa[np][3] = pack2h(p12, p13);   // a3: (r+8, k+8 pair)
        }

        // ---- O += P.V (fp32 acc) ----
        #pragma unroll
        for (int jn = 0; jn < 4; jn++) {
            #pragma unroll
            for (int s = 0; s < 4; s++) {
                uint32_t off = (uint32_t)((s * 16 + vRow) * LDV + jn * 16 + vCol) * 2;
                uint32_t h0, h1, h2, h3;
                ldm_x4_t(h0, h1, h2, h3, vhb + off);
                uint32_t bvh0[2] = {h0, h1}, bvh1[2] = {h2, h3};
                mma_f16(oacc[jn * 2],     pa[s], bvh0);
                mma_f16(oacc[jn * 2 + 1], pa[s], bvh1);
            }
        }
        __syncthreads();
        if (kt + 2 < 16) issue(kt + 2, kt & 1);
        CP_COMMIT();
    }

    // ---- normalize + store o (fp16) ----
    l0 += __shfl_xor_sync(0xFFFFFFFFu, l0, 1);
    l0 += __shfl_xor_sync(0xFFFFFFFFu, l0, 2);
    l1 += __shfl_xor_sync(0xFFFFFFFFu, l1, 1);
    l1 += __shfl_xor_sync(0xFFFFFFFFu, l1, 2);
    const float inv0 = 1.0f / l0;
    const float inv1 = 1.0f / l1;

    const int b = bh / Hv;
    const int h = bh - b * Hv;
    const int qg0 = blockIdx.x * 128 + wid * 16 + (lane >> 2);
    const size_t o0 = ((size_t)(b * Nv + qg0)) * Cv + h * HD + kcol;
    const size_t o1 = o0 + 8 * (size_t)Cv;
    #pragma unroll
    for (int j = 0; j < 8; j++) {
        *(uint32_t*)(g_oh + o0 + j * 8) = pack2h(oacc[j][0] * inv0, oacc[j][1] * inv0);
        *(uint32_t*)(g_oh + o1 + j * 8) = pack2h(oacc[j][2] * inv1, oacc[j][3] * inv1);
    }
}

// ======================= launch =======================
extern "C" void kernel_launch(void* const* d_in, const int* in_sizes, int n_in,
                              void* d_out, int out_size) {
    const float* x      = (const float*)d_in[0];
    const int*   label  = (const int*)d_in[1];
    const float* alpha  = (const float*)d_in[2];
    const float* qkv_w  = (const float*)d_in[3];
    const float* qkv_b  = (const float*)d_in[4];
    const float* proj_w = (const float*)d_in[5];
    const float* proj_b = (const float*)d_in[6];
    float* out = (float*)d_out;

    cudaFuncSetAttribute(qkv_gemm, cudaFuncAttributeMaxDynamicSharedMemorySize, SM_BYTES);
    cudaFuncSetAttribute(proj_gemm, cudaFuncAttributeMaxDynamicSharedMemorySize, SM_BYTES);
    cudaFuncSetAttribute(attn_mma, cudaFuncAttributeMaxDynamicSharedMemorySize, ASM_BYTES);

    prep_kernel<<<(N8TOT + 1023) / 1024, 256>>>(x, qkv_w, proj_w, alpha, label);
    qkv_gemm<<<dim3(C3 / 128, MT / 128), 256, SM_BYTES>>>(qkv_b);
    attn_mma<<<dim3(Nv / 128, Bv * Hv), 256, ASM_BYTES>>>();
    proj_gemm<<<dim3(Cv / 128, MT / 128), 256, SM_BYTES>>>(proj_b, out);
}

// round 16
// speedup vs baseline: 1.0063x; 1.0063x over previous
#include <cuda_runtime.h>
#include <cuda_fp16.h>
#include <cstdint>

#define Bv 16
#define Nv 1024
#define Cv 768
#define Hv 12
#define HD 64
#define C3 2304
#define MT (Bv*Nv)   // 16384

// ======================= device scratch =======================
__device__ float g_sig[Bv * C3];
__device__ __half g_xh[(size_t)MT * Cv];
__device__ __half g_w1h[(size_t)C3 * Cv];
__device__ __half g_w2h[(size_t)Cv * Cv];
__device__ __half g_qh[(size_t)MT * Cv];   // (b,h,n,hd) fp16
__device__ __half g_kh[(size_t)MT * Cv];
__device__ __half g_vh[(size_t)MT * Cv];
__device__ __half g_oh[(size_t)MT * Cv];   // (b,n,c) fp16

// ======================= PTX helpers (baseline ISA only) =======================
__device__ __forceinline__ uint32_t smem_u32(const void* p) {
    uint32_t a;
    asm("{ .reg .u64 t; cvta.to.shared.u64 t, %1; cvt.u32.u64 %0, t; }" : "=r"(a) : "l"(p));
    return a;
}
__device__ __forceinline__ void ldm_x4(uint32_t& r0, uint32_t& r1, uint32_t& r2, uint32_t& r3,
                                       uint32_t addr) {
    asm volatile("ldmatrix.sync.aligned.m8n8.x4.shared.b16 {%0,%1,%2,%3}, [%4];"
                 : "=r"(r0), "=r"(r1), "=r"(r2), "=r"(r3) : "r"(addr));
}
__device__ __forceinline__ void ldm_x4_t(uint32_t& r0, uint32_t& r1, uint32_t& r2, uint32_t& r3,
                                         uint32_t addr) {
    asm volatile("ldmatrix.sync.aligned.m8n8.x4.trans.shared.b16 {%0,%1,%2,%3}, [%4];"
                 : "=r"(r0), "=r"(r1), "=r"(r2), "=r"(r3) : "r"(addr));
}
__device__ __forceinline__ void mma_f16(float* d, const uint32_t* a, const uint32_t* b) {
    asm volatile(
        "mma.sync.aligned.m16n8k16.row.col.f32.f16.f16.f32 "
        "{%0,%1,%2,%3}, {%4,%5,%6,%7}, {%8,%9}, {%0,%1,%2,%3};"
        : "+f"(d[0]), "+f"(d[1]), "+f"(d[2]), "+f"(d[3])
        : "r"(a[0]), "r"(a[1]), "r"(a[2]), "r"(a[3]), "r"(b[0]), "r"(b[1]));
}
__device__ __forceinline__ void cp16(uint32_t dst, const void* src) {
    asm volatile("cp.async.cg.shared.global [%0], [%1], 16;" :: "r"(dst), "l"(src));
}
#define CP_COMMIT() asm volatile("cp.async.commit_group;" ::: "memory")
#define CP_WAIT1()  asm volatile("cp.async.wait_group 1;" ::: "memory")

__device__ __forceinline__ uint32_t pack2h(float x, float y) {
    __half2 h = __floats2half2_rn(x, y);
    return *(uint32_t*)&h;
}
__device__ __forceinline__ float fexp2(float x) {
    float r;
    asm("ex2.approx.ftz.f32 %0, %1;" : "=f"(r) : "f"(x));
    return r;
}
#define EXSCALE 0.1803368801f   // 0.125 * log2(e)

// ======================= prep: gate + converts, straight-line MLP=8 =======================
#define N8X  (MT * Cv / 8)          // 1572864 = 1536*1024
#define N8W1 (C3 * Cv / 8)          // 221184
#define N8W2 (Cv * Cv / 8)          // 73728
#define N8TOT (N8X + N8W1 + N8W2)   // 1867776 = 1824*1024 exactly
#define PREP_BLOCKS (N8TOT / 1024)  // 1824
#define GATEN (Bv * C3)             // 36864

__global__ void prep_kernel(const float* __restrict__ x,
                            const float* __restrict__ w1,
                            const float* __restrict__ w2,
                            const float* __restrict__ alpha,
                            const int* __restrict__ label) {
    const int base = blockIdx.x * 1024 + threadIdx.x;
    // 4 items x (2 independent LDG.128) = 8 outstanding loads, no bounds checks
    float4 v[4][2];
    const float4* sp[4];
    __half* dp[4];
    size_t jj[4];
    #pragma unroll
    for (int it = 0; it < 4; it++) {
        int i = base + it * 256;
        const float* src;
        __half* dst;
        size_t j;
        if (i < N8X)            { src = x;  dst = g_xh;  j = i; }
        else if (i < N8X + N8W1){ src = w1; dst = g_w1h; j = i - N8X; }
        else                    { src = w2; dst = g_w2h; j = i - N8X - N8W1; }
        sp[it] = (const float4*)src + j * 2;
        dp[it] = dst;
        jj[it] = j;
    }
    #pragma unroll
    for (int it = 0; it < 4; it++) {
        v[it][0] = sp[it][0];
        v[it][1] = sp[it][1];
    }
    #pragma unroll
    for (int it = 0; it < 4; it++) {
        float4 v0 = v[it][0], v1 = v[it][1];
        __half h[8] = {
            __float2half_rn(v0.x), __float2half_rn(v0.y), __float2half_rn(v0.z), __float2half_rn(v0.w),
            __float2half_rn(v1.x), __float2half_rn(v1.y), __float2half_rn(v1.z), __float2half_rn(v1.w)
        };
        *(uint4*)(dp[it] + jj[it] * 8) = *(uint4*)h;
    }
    // gate (only low blocks hit this)
    #pragma unroll
    for (int it = 0; it < 4; it++) {
        int i = base + it * 256;
        if (i < GATEN) {
            int b = i / C3;
            int d = i - b * C3;
            float a = alpha[(size_t)label[b] * C3 + d];
            g_sig[i] = 1.0f / (1.0f + __expf(-a));
        }
    }
}

// ======================= qkv GEMM: 128x128 tile, 2-stage (R14 config) =======================
#define LDP 40
#define TILEB (128*LDP*2)           // 10240
#define BUFB  (2*TILEB)             // 20480
#define SM_BYTES (2*BUFB)           // 40960

__global__ __launch_bounds__(256, 2)
void qkv_gemm(const float* __restrict__ bias) {
    extern __shared__ __align__(16) char sm[];
    const uint32_t sb = smem_u32(sm);

    const int tid = threadIdx.x;
    const int wid = tid >> 5;
    const int lane = tid & 31;
    const int m0 = blockIdx.y * 128;
    const int n0 = blockIdx.x * 128;
    const int wm = (wid & 1) * 64;
    const int wn = (wid >> 1) * 32;

    const int srow = tid >> 2;
    const int sg = tid & 3;

    const int grp = lane >> 3, lr = lane & 7;
    const int aRow = (grp & 1) * 8 + lr;
    const int aCol = (grp >> 1) * 8;
    const int bRow = (grp >> 1) * 8 + lr;
    const int bCol = (grp & 1) * 8;

    float acc[4][4][4] = {};

    auto issue = [&](int kc, int bsel) {
        const int k0 = kc * 32;
        const __half* s0 = g_xh + (size_t)m0 * Cv + k0;
        const __half* s1 = g_w1h + (size_t)n0 * Cv + k0;
        const uint32_t db = sb + bsel * BUFB;
        #pragma unroll
        for (int j = 0; j < 2; j++) {
            int row = srow + j * 64;
            uint32_t doff = (uint32_t)(row * LDP + sg * 8) * 2;
            size_t goff = (size_t)row * Cv + sg * 8;
            cp16(db + 0 * TILEB + doff, s0 + goff);
            cp16(db + 1 * TILEB + doff, s1 + goff);
        }
    };

    issue(0, 0); CP_COMMIT();
    issue(1, 1); CP_COMMIT();

    for (int kc = 0; kc < 24; kc++) {
        CP_WAIT1();
        __syncthreads();
        const uint32_t db = sb + (kc & 1) * BUFB;

        #pragma unroll
        for (int kk = 0; kk < 2; kk++) {
            uint32_t bh[4][2];
            #pragma unroll
            for (int np = 0; np < 2; np++) {
                uint32_t off = (uint32_t)((wn + np * 16 + bRow) * LDP + kk * 16 + bCol) * 2;
                uint32_t r0, r1, r2, r3;
                ldm_x4(r0, r1, r2, r3, db + TILEB + off);
                bh[np * 2][0] = r0; bh[np * 2][1] = r1;
                bh[np * 2 + 1][0] = r2; bh[np * 2 + 1][1] = r3;
            }
            #pragma unroll
            for (int mi = 0; mi < 4; mi++) {
                uint32_t ah[4];
                uint32_t off = (uint32_t)((wm + mi * 16 + aRow) * LDP + kk * 16 + aCol) * 2;
                ldm_x4(ah[0], ah[1], ah[2], ah[3], db + off);
                #pragma unroll
                for (int nj = 0; nj < 4; nj++)
                    mma_f16(acc[mi][nj], ah, bh[nj]);
            }
        }
        __syncthreads();
        if (kc + 2 < 24) issue(kc + 2, kc & 1);
        CP_COMMIT();
    }

    const int tq = n0 / Cv;
    #pragma unroll
    for (int mi = 0; mi < 4; mi++) {
        #pragma unroll
        for (int nj = 0; nj < 4; nj++) {
            int r = m0 + wm + mi * 16 + (lane >> 2);
            int c = n0 + wn + nj * 8 + 2 * (lane & 3);
            #pragma unroll
            for (int half = 0; half < 2; half++) {
                int rr = r + half * 8;
                float v0 = acc[mi][nj][half * 2 + 0];
                float v1 = acc[mi][nj][half * 2 + 1];
                float2 bi = *(const float2*)(bias + c);
                int b = rr >> 10;
                int n = rr & 1023;
                float2 sg2 = *(const float2*)(g_sig + b * C3 + c);
                float ox = (v0 + bi.x) * sg2.x;
                float oy = (v1 + bi.y) * sg2.y;
                int rem = c - tq * Cv;
                int h = rem >> 6;
                int e = rem & 63;
                size_t idx = ((size_t)(b * Hv + h) * Nv + n) * HD + e;
                __half* dst = (tq == 0) ? g_qh : (tq == 1) ? g_kh : g_vh;
                *(uint32_t*)(dst + idx) = pack2h(ox, oy);
            }
        }
    }
}

// ======================= proj GEMM: 128x128 tile, 2-stage (R14 config) =======================
__global__ __launch_bounds__(256, 2)
void proj_gemm(const float* __restrict__ bias, float* __restrict__ out) {
    extern __shared__ __align__(16) char sm[];
    const uint32_t sb = smem_u32(sm);

    const int tid = threadIdx.x;
    const int wid = tid >> 5;
    const int lane = tid & 31;
    const int m0 = blockIdx.y * 128;
    const int n0 = blockIdx.x * 128;
    const int wm = (wid & 1) * 64;
    const int wn = (wid >> 1) * 32;

    const int srow = tid >> 2;
    const int sg = tid & 3;

    const int grp = lane >> 3, lr = lane & 7;
    const int aRow = (grp & 1) * 8 + lr;
    const int aCol = (grp >> 1) * 8;
    const int bRow = (grp >> 1) * 8 + lr;
    const int bCol = (grp & 1) * 8;

    float acc[4][4][4] = {};

    auto issue = [&](int kc, int bsel) {
        const int k0 = kc * 32;
        const __half* s0 = g_oh + (size_t)m0 * Cv + k0;
        const __half* s1 = g_w2h + (size_t)n0 * Cv + k0;
        const uint32_t db = sb + bsel * BUFB;
        #pragma unroll
        for (int j = 0; j < 2; j++) {
            int row = srow + j * 64;
            uint32_t doff = (uint32_t)(row * LDP + sg * 8) * 2;
            size_t goff = (size_t)row * Cv + sg * 8;
            cp16(db + 0 * TILEB + doff, s0 + goff);
            cp16(db + 1 * TILEB + doff, s1 + goff);
        }
    };

    issue(0, 0); CP_COMMIT();
    issue(1, 1); CP_COMMIT();

    for (int kc = 0; kc < 24; kc++) {
        CP_WAIT1();
        __syncthreads();
        const uint32_t db = sb + (kc & 1) * BUFB;

        #pragma unroll
        for (int kk = 0; kk < 2; kk++) {
            uint32_t bh[4][2];
            #pragma unroll
            for (int np = 0; np < 2; np++) {
                uint32_t off = (uint32_t)((wn + np * 16 + bRow) * LDP + kk * 16 + bCol) * 2;
                uint32_t r0, r1, r2, r3;
                ldm_x4(r0, r1, r2, r3, db + TILEB + off);
                bh[np * 2][0] = r0; bh[np * 2][1] = r1;
                bh[np * 2 + 1][0] = r2; bh[np * 2 + 1][1] = r3;
            }
            #pragma unroll
            for (int mi = 0; mi < 4; mi++) {
                uint32_t ah[4];
                uint32_t off = (uint32_t)((wm + mi * 16 + aRow) * LDP + kk * 16 + aCol) * 2;
                ldm_x4(ah[0], ah[1], ah[2], ah[3], db + off);
                #pragma unroll
                for (int nj = 0; nj < 4; nj++)
                    mma_f16(acc[mi][nj], ah, bh[nj]);
            }
        }
        __syncthreads();
        if (kc + 2 < 24) issue(kc + 2, kc & 1);
        CP_COMMIT();
    }

    #pragma unroll
    for (int mi = 0; mi < 4; mi++) {
        #pragma unroll
        for (int nj = 0; nj < 4; nj++) {
            int r = m0 + wm + mi * 16 + (lane >> 2);
            int c = n0 + wn + nj * 8 + 2 * (lane & 3);
            #pragma unroll
            for (int half = 0; half < 2; half++) {
                int rr = r + half * 8;
                float2 bi = *(const float2*)(bias + c);
                float2 o;
                o.x = acc[mi][nj][half * 2 + 0] + bi.x;
                o.y = acc[mi][nj][half * 2 + 1] + bi.y;
                *(float2*)(out + (size_t)rr * Cv + c) = o;
            }
        }
    }
}

// ======================= fp16 HMMA flash attention: 2-stage, fp32 acc (R14 config) =======================
#define LDV 72
#define VTILEB (64*LDV*2)           // 9216
#define ABUFB (2*VTILEB)            // 18432
#define ASM_BYTES (2*ABUFB)         // 36864

__global__ __launch_bounds__(256, 2) void attn_mma() {
    extern __shared__ __align__(16) char sm[];
    const uint32_t sb = smem_u32(sm);

    const int tid = threadIdx.x;
    const int wid = tid >> 5;
    const int lane = tid & 31;
    const int bh = blockIdx.y;
    const size_t head_base = (size_t)bh * Nv * HD;
    const int q0 = blockIdx.x * 128 + wid * 16;

    const int grp = lane >> 3, lr = lane & 7;
    const int bRow = (grp >> 1) * 8 + lr;
    const int bCol = (grp & 1) * 8;
    const int vRow = lane & 15;
    const int vCol = (lane >> 4) * 8;

    const int srow = tid >> 3;
    const int sg = tid & 7;

    // ---- Q fragments (fp16) direct from gmem ----
    const int qrow0 = q0 + (lane >> 2);
    const int kcol = (lane & 3) * 2;
    uint32_t qh[4][4];
    {
        const size_t base0 = head_base + (size_t)qrow0 * HD;
        const size_t base1 = base0 + 8 * HD;
        #pragma unroll
        for (int s = 0; s < 4; s++) {
            qh[s][0] = *(const uint32_t*)(g_qh + base0 + s * 16 + kcol);
            qh[s][1] = *(const uint32_t*)(g_qh + base1 + s * 16 + kcol);
            qh[s][2] = *(const uint32_t*)(g_qh + base0 + s * 16 + 8 + kcol);
            qh[s][3] = *(const uint32_t*)(g_qh + base1 + s * 16 + 8 + kcol);
        }
    }

    auto issue = [&](int kt, int bsel) {
        const __half* s0 = g_kh + head_base + (size_t)kt * 64 * HD;
        const __half* s1 = g_vh + head_base + (size_t)kt * 64 * HD;
        const uint32_t db = sb + bsel * ABUFB;
        #pragma unroll
        for (int j = 0; j < 2; j++) {
            int row = srow + j * 32;
            uint32_t doff = (uint32_t)(row * LDV + sg * 8) * 2;
            size_t goff = (size_t)row * HD + sg * 8;
            cp16(db + 0 * VTILEB + doff, s0 + goff);
            cp16(db + 1 * VTILEB + doff, s1 + goff);
        }
    };

    float oacc[8][4] = {};
    float l0 = 0.f, l1 = 0.f;

    issue(0, 0); CP_COMMIT();
    issue(1, 1); CP_COMMIT();

    for (int kt = 0; kt < 16; kt++) {
        CP_WAIT1();
        __syncthreads();
        const uint32_t db = sb + (kt & 1) * ABUFB;
        const uint32_t khb = db;
        const uint32_t vhb = db + VTILEB;

        // ---- S = Q.K^T, exp2, pack P ----
        uint32_t pa[4][4];
        #pragma unroll
        for (int np = 0; np < 4; np++) {
            float sc0[4] = {}, sc1[4] = {};
            #pragma unroll
            for (int s = 0; s < 4; s++) {
                uint32_t off = (uint32_t)((np * 16 + bRow) * LDV + s * 16 + bCol) * 2;
                uint32_t h0, h1, h2, h3;
                ldm_x4(h0, h1, h2, h3, khb + off);
                uint32_t bh0[2] = {h0, h1}, bh1[2] = {h2, h3};
                mma_f16(sc0, qh[s], bh0);
                mma_f16(sc1, qh[s], bh1);
            }
            float p00 = fexp2(sc0[0] * EXSCALE), p01 = fexp2(sc0[1] * EXSCALE);
            float p02 = fexp2(sc0[2] * EXSCALE), p03 = fexp2(sc0[3] * EXSCALE);
            float p10 = fexp2(sc1[0] * EXSCALE), p11 = fexp2(sc1[1] * EXSCALE);
            float p12 = fexp2(sc1[2] * EXSCALE), p13 = fexp2(sc1[3] * EXSCALE);
            l0 += (p00 + p01) + (p10 + p11);
            l1 += (p02 + p03) + (p12 + p13);
            pa[np][0] = pack2h(p00, p01);
            pa[np][1] = pack2h(p02, p03);
            pa[np][2] = pack2h(p10, p11);
            pa[np][3] = pack2h(p12, p13);
        }

        // ---- O += P.V ----
        #pragma unroll
        for (int jn = 0; jn < 4; jn++) {
            #pragma unroll
            for (int s = 0; s < 4; s++) {
                uint32_t off = (uint32_t)((s * 16 + vRow) * LDV + jn * 16 + vCol) * 2;
                uint32_t h0, h1, h2, h3;
                ldm_x4_t(h0, h1, h2, h3, vhb + off);
                uint32_t bvh0[2] = {h0, h1}, bvh1[2] = {h2, h3};
                mma_f16(oacc[jn * 2],     pa[s], bvh0);
                mma_f16(oacc[jn * 2 + 1], pa[s], bvh1);
            }
        }
        __syncthreads();
        if (kt + 2 < 16) issue(kt + 2, kt & 1);
        CP_COMMIT();
    }

    // ---- normalize + store o (fp16) ----
    l0 += __shfl_xor_sync(0xFFFFFFFFu, l0, 1);
    l0 += __shfl_xor_sync(0xFFFFFFFFu, l0, 2);
    l1 += __shfl_xor_sync(0xFFFFFFFFu, l1, 1);
    l1 += __shfl_xor_sync(0xFFFFFFFFu, l1, 2);
    const float inv0 = 1.0f / l0;
    const float inv1 = 1.0f / l1;

    const int b = bh / Hv;
    const int h = bh - b * Hv;
    const int qg0 = blockIdx.x * 128 + wid * 16 + (lane >> 2);
    const size_t o0 = ((size_t)(b * Nv + qg0)) * Cv + h * HD + kcol;
    const size_t o1 = o0 + 8 * (size_t)Cv;
    #pragma unroll
    for (int j = 0; j < 8; j++) {
        *(uint32_t*)(g_oh + o0 + j * 8) = pack2h(oacc[j][0] * inv0, oacc[j][1] * inv0);
        *(uint32_t*)(g_oh + o1 + j * 8) = pack2h(oacc[j][2] * inv1, oacc[j][3] * inv1);
    }
}

// ======================= launch =======================
extern "C" void kernel_launch(void* const* d_in, const int* in_sizes, int n_in,
                              void* d_out, int out_size) {
    const float* x      = (const float*)d_in[0];
    const int*   label  = (const int*)d_in[1];
    const float* alpha  = (const float*)d_in[2];
    const float* qkv_w  = (const float*)d_in[3];
    const float* qkv_b  = (const float*)d_in[4];
    const float* proj_w = (const float*)d_in[5];
    const float* proj_b = (const float*)d_in[6];
    float* out = (float*)d_out;

    cudaFuncSetAttribute(qkv_gemm, cudaFuncAttributeMaxDynamicSharedMemorySize, SM_BYTES);
    cudaFuncSetAttribute(proj_gemm, cudaFuncAttributeMaxDynamicSharedMemorySize, SM_BYTES);
    cudaFuncSetAttribute(attn_mma, cudaFuncAttributeMaxDynamicSharedMemorySize, ASM_BYTES);

    prep_kernel<<<PREP_BLOCKS, 256>>>(x, qkv_w, proj_w, alpha, label);
    qkv_gemm<<<dim3(C3 / 128, MT / 128), 256, SM_BYTES>>>(qkv_b);
    attn_mma<<<dim3(Nv / 128, Bv * Hv), 256, ASM_BYTES>>>();
    proj_gemm<<<dim3(Cv / 128, MT / 128), 256, SM_BYTES>>>(proj_b, out);
}